// round 16
// baseline (speedup 1.0000x reference)
#include <cuda_runtime.h>
#include <cuda_fp16.h>
#include <math.h>
#include <stdint.h>

#define NB   4096
#define TT   16
#define HID  256
#define WHAT 50
#define WHERE 3
#define GG   20
#define IMH  50
#define IMW  50
#define MALL (NB * TT)   // 65536

#define KREL 736   // 718 real
#define KTEM 640   // 615 real (h_rela dedup)
#define NCREL 23
#define NCTEM 20
#define KGE1 416   // 400 real
#define KGE2 224   // 200 real
#define KLW  576   // 562 real
#define NCGE1 13
#define NCGE2 7
#define NCLW 18

// ---------------- scratch ----------------
__device__ float g_h_rela[NB * HID];
__device__ float g_c_rela[NB * HID];
__device__ float g_zw_cur[NB * WHERE];
__device__ float g_zwt_zero[NB * WHAT];
__device__ float g_gates[NB * 1024];
__device__ float g_mt[NB * 100];
__device__ float g_msw_where[NB * 6];
// fp16 split activations
__device__ __align__(16) __half g_gl_hi[NB * KGE1];
__device__ __align__(16) __half g_gl_lo[NB * KGE1];
__device__ __align__(16) __half g_h1_hi[NB * KGE2];
__device__ __align__(16) __half g_h1_lo[NB * KGE2];
__device__ __align__(16) __half g_lw_hi[NB * KLW];
__device__ __align__(16) __half g_lw_lo[NB * KLW];
__device__ __align__(16) __half g_rel_hi[NB * KREL];
__device__ __align__(16) __half g_rel_lo[NB * KREL];
__device__ __align__(16) __half g_tem_hi[NB * KTEM];
__device__ __align__(16) __half g_tem_lo[NB * KTEM];
// batched glimpse-1 path (all 16 steps)
__device__ __align__(16) __half g_glA_hi[MALL * KGE1];
__device__ __align__(16) __half g_glA_lo[MALL * KGE1];
__device__ __align__(16) __half g_h1A_hi[MALL * KGE2];
__device__ __align__(16) __half g_h1A_lo[MALL * KGE2];
__device__ __align__(16) __half g_enc1_hi[MALL * 100];
__device__ __align__(16) __half g_enc1_lo[MALL * 100];
// weights (split, padded)
__device__ __align__(16) __half g_Wrel_hi[1024 * KREL];
__device__ __align__(16) __half g_Wrel_lo[1024 * KREL];
__device__ __align__(16) __half g_Wtem_hi[1024 * KTEM];
__device__ __align__(16) __half g_Wtem_lo[1024 * KTEM];
__device__ __align__(16) __half g_Wge1_hi[256 * KGE1];
__device__ __align__(16) __half g_Wge1_lo[256 * KGE1];
__device__ __align__(16) __half g_Wge2_hi[128 * KGE2];
__device__ __align__(16) __half g_Wge2_lo[128 * KGE2];
__device__ __align__(16) __half g_Wlw_hi[128 * KLW];
__device__ __align__(16) __half g_Wlw_lo[128 * KLW];
__device__ float g_brel[1024];
__device__ float g_btem[1024];

// ---------------- helpers ----------------
__device__ __forceinline__ float sigmoidf_(float x) { return 1.f / (1.f + expf(-x)); }
__device__ __forceinline__ float softplusf_(float x) {
    return x > 0.f ? x + log1pf(expf(-x)) : log1pf(expf(x));
}
__device__ __forceinline__ float warp_sum(float v) {
    #pragma unroll
    for (int o = 16; o > 0; o >>= 1) v += __shfl_xor_sync(0xffffffffu, v, o);
    return v;
}
__device__ __forceinline__ uint32_t smem_u32(const void* p) {
    uint32_t a;
    asm("{ .reg .u64 t; cvta.to.shared.u64 t, %1; cvt.u32.u64 %0, t; }" : "=r"(a) : "l"(p));
    return a;
}
__device__ __forceinline__ void split_h(float v, __half* hi, __half* lo) {
    __half h = __float2half_rn(v);
    *hi = h;
    *lo = __float2half_rn(v - __half2float(h));
}

#define CP_ASYNC16(dst, src) \
    asm volatile("cp.async.cg.shared.global [%0], [%1], 16;" :: "r"(dst), "l"(src))
#define CP_COMMIT() asm volatile("cp.async.commit_group;")
#define CP_WAIT1()  asm volatile("cp.async.wait_group 1;")

#define MMA_F16(d, a, b0, b1) \
    asm volatile("mma.sync.aligned.m16n8k16.row.col.f32.f16.f16.f32 " \
        "{%0,%1,%2,%3}, {%4,%5,%6,%7}, {%8,%9}, {%0,%1,%2,%3};" \
        : "+f"(d[0]), "+f"(d[1]), "+f"(d[2]), "+f"(d[3]) \
        : "r"(a[0]), "r"(a[1]), "r"(a[2]), "r"(a[3]), "r"(b0), "r"(b1))

#define LDSM_X4(r0, r1, r2, r3, addr) \
    asm volatile("ldmatrix.sync.aligned.m8n8.x4.shared.b16 {%0,%1,%2,%3}, [%4];" \
        : "=r"(r0), "=r"(r1), "=r"(r2), "=r"(r3) : "r"(addr))

// ---------------- fp16x3 GEMM (big): C[4096,1024] = A @ W^T + bias ----------------
// 2-stage cp.async ring, 2 CTAs/SM, ldmatrix fragment loads.
#define H_MAT_B   10240
#define H_STAGE_B (4 * H_MAT_B)
#define H_SMEM_B  (2 * H_STAGE_B)   // 81920

__global__ void __launch_bounds__(256, 2) gemm_h3(
    const __half* __restrict__ Ahi, const __half* __restrict__ Alo,
    const __half* __restrict__ Bhi, const __half* __restrict__ Blo,
    const float* __restrict__ bias, float* __restrict__ C, int K, int NC)
{
    extern __shared__ char smem[];
    const uint32_t sbase = smem_u32(smem);
    const int tid = threadIdx.x;
    const int wid = tid >> 5, lane = tid & 31;
    const int wm = wid >> 2, wn = wid & 3;
    const int qr = lane >> 2, qc = lane & 3;
    const int bm = blockIdx.y * 128, bn = blockIdx.x * 128;

    // ldmatrix lane-relative byte offsets within a matrix tile
    const int ltile = lane >> 3, lrow = lane & 7;
    uint32_t aoff[4];
    #pragma unroll
    for (int i = 0; i < 4; i++)
        aoff[i] = (uint32_t)((wm * 64 + i * 16 + (ltile & 1) * 8 + lrow) * 80 + (ltile >> 1) * 16);
    const uint32_t boff = (uint32_t)((wn * 32 + ltile * 8 + lrow) * 80);

    auto issue = [&](int c, int s) {
        const uint32_t stb = sbase + (uint32_t)s * H_STAGE_B;
        const __half* srcs[4] = {
            Ahi + (size_t)bm * K + (size_t)c * 32,
            Alo + (size_t)bm * K + (size_t)c * 32,
            Bhi + (size_t)bn * K + (size_t)c * 32,
            Blo + (size_t)bn * K + (size_t)c * 32
        };
        #pragma unroll
        for (int mat = 0; mat < 4; mat++) {
            const __half* sp = srcs[mat];
            #pragma unroll
            for (int i = 0; i < 2; i++) {
                int g = tid + i * 256;
                int row = g >> 2, q = g & 3;
                uint32_t doff = stb + (uint32_t)mat * H_MAT_B + (uint32_t)(row * 80 + q * 16);
                CP_ASYNC16(doff, sp + (size_t)row * K + q * 8);
            }
        }
    };

    issue(0, 0); CP_COMMIT();
    issue(1, 1); CP_COMMIT();

    float acc[4][4][4] = {};

    for (int c = 0; c < NC; c++) {
        const int s = c & 1;
        CP_WAIT1();
        __syncthreads();

        const uint32_t stb = sbase + (uint32_t)s * H_STAGE_B;

        #pragma unroll
        for (int ks = 0; ks < 2; ks++) {
            const uint32_t kofs = (uint32_t)(ks * 32);
            uint32_t ah[4][4], al[4][4];
            uint32_t b0h[4], b1h[4], b0l[4], b1l[4];
            #pragma unroll
            for (int i = 0; i < 4; i++) {
                LDSM_X4(ah[i][0], ah[i][1], ah[i][2], ah[i][3], stb + aoff[i] + kofs);
                LDSM_X4(al[i][0], al[i][1], al[i][2], al[i][3],
                        stb + H_MAT_B + aoff[i] + kofs);
            }
            LDSM_X4(b0h[0], b0h[1], b0h[2], b0h[3], stb + 2 * H_MAT_B + boff + kofs);
            LDSM_X4(b1h[0], b1h[1], b1h[2], b1h[3], stb + 2 * H_MAT_B + boff + kofs + 16);
            LDSM_X4(b0l[0], b0l[1], b0l[2], b0l[3], stb + 3 * H_MAT_B + boff + kofs);
            LDSM_X4(b1l[0], b1l[1], b1l[2], b1l[3], stb + 3 * H_MAT_B + boff + kofs + 16);
            #pragma unroll
            for (int i = 0; i < 4; i++)
                #pragma unroll
                for (int j = 0; j < 4; j++) {
                    MMA_F16(acc[i][j], ah[i], b0h[j], b1h[j]);
                    MMA_F16(acc[i][j], al[i], b0h[j], b1h[j]);
                    MMA_F16(acc[i][j], ah[i], b0l[j], b1l[j]);
                }
        }

        __syncthreads();
        if (c + 2 < NC) { issue(c + 2, s); CP_COMMIT(); }
    }

    #pragma unroll
    for (int i = 0; i < 4; i++) {
        int row = bm + wm * 64 + i * 16 + qr;
        #pragma unroll
        for (int j = 0; j < 4; j++) {
            int col = bn + wn * 32 + j * 8 + qc * 2;
            float b0 = bias[col], b1 = bias[col + 1];
            *(float2*)&C[(size_t)row * 1024 + col] =
                make_float2(acc[i][j][0] + b0, acc[i][j][1] + b1);
            *(float2*)&C[(size_t)(row + 8) * 1024 + col] =
                make_float2(acc[i][j][2] + b0, acc[i][j][3] + b1);
        }
    }
}

// ---------------- fp16x3 GEMM (small, 64x64): mode 0 f32; 1 relu+split; 2 split ----
#define S_MAT_B   5120
#define S_STAGE_B (4 * S_MAT_B)
#define S_SMEM_B  (3 * S_STAGE_B)

__global__ void __launch_bounds__(128) gemm_h3s(
    const __half* __restrict__ Ahi, const __half* __restrict__ Alo,
    const __half* __restrict__ Bhi, const __half* __restrict__ Blo,
    const float* __restrict__ bias, float* __restrict__ C,
    __half* __restrict__ Chi, __half* __restrict__ Clo,
    int K, int NC, int NN, int ldc, int mode)
{
    extern __shared__ char smem[];
    const uint32_t sbase = smem_u32(smem);
    const int tid = threadIdx.x;
    const int wid = tid >> 5, lane = tid & 31;
    const int wm = wid >> 1, wn = wid & 1;
    const int qr = lane >> 2, qc = lane & 3;
    const int bm = blockIdx.y * 64, bn = blockIdx.x * 64;

    const int ltile = lane >> 3, lrow = lane & 7;
    uint32_t aoff[2];
    #pragma unroll
    for (int i = 0; i < 2; i++)
        aoff[i] = (uint32_t)((wm * 32 + i * 16 + (ltile & 1) * 8 + lrow) * 80 + (ltile >> 1) * 16);
    const uint32_t boff = (uint32_t)((wn * 32 + ltile * 8 + lrow) * 80);

    auto issue = [&](int c, int s) {
        const uint32_t stb = sbase + (uint32_t)s * S_STAGE_B;
        const __half* srcs[4] = {
            Ahi + (size_t)bm * K + (size_t)c * 32,
            Alo + (size_t)bm * K + (size_t)c * 32,
            Bhi + (size_t)bn * K + (size_t)c * 32,
            Blo + (size_t)bn * K + (size_t)c * 32
        };
        #pragma unroll
        for (int mat = 0; mat < 4; mat++) {
            const __half* sp = srcs[mat];
            #pragma unroll
            for (int i = 0; i < 2; i++) {
                int g = tid + i * 128;
                int row = g >> 2, q = g & 3;
                uint32_t doff = stb + (uint32_t)mat * S_MAT_B + (uint32_t)(row * 80 + q * 16);
                CP_ASYNC16(doff, sp + (size_t)row * K + q * 8);
            }
        }
    };

    issue(0, 0); CP_COMMIT();
    if (NC > 1) issue(1, 1);
    CP_COMMIT();

    float acc[2][4][4] = {};

    for (int c = 0; c < NC; c++) {
        const int s = c - (c / 3) * 3;
        CP_WAIT1();
        __syncthreads();
        if (c + 2 < NC) issue(c + 2, (c + 2) % 3);
        CP_COMMIT();

        const uint32_t stb = sbase + (uint32_t)s * S_STAGE_B;

        #pragma unroll
        for (int ks = 0; ks < 2; ks++) {
            const uint32_t kofs = (uint32_t)(ks * 32);
            uint32_t ah[2][4], al[2][4];
            uint32_t b0h[4], b1h[4], b0l[4], b1l[4];
            #pragma unroll
            for (int i = 0; i < 2; i++) {
                LDSM_X4(ah[i][0], ah[i][1], ah[i][2], ah[i][3], stb + aoff[i] + kofs);
                LDSM_X4(al[i][0], al[i][1], al[i][2], al[i][3],
                        stb + S_MAT_B + aoff[i] + kofs);
            }
            LDSM_X4(b0h[0], b0h[1], b0h[2], b0h[3], stb + 2 * S_MAT_B + boff + kofs);
            LDSM_X4(b1h[0], b1h[1], b1h[2], b1h[3], stb + 2 * S_MAT_B + boff + kofs + 16);
            LDSM_X4(b0l[0], b0l[1], b0l[2], b0l[3], stb + 3 * S_MAT_B + boff + kofs);
            LDSM_X4(b1l[0], b1l[1], b1l[2], b1l[3], stb + 3 * S_MAT_B + boff + kofs + 16);
            #pragma unroll
            for (int i = 0; i < 2; i++)
                #pragma unroll
                for (int j = 0; j < 4; j++) {
                    MMA_F16(acc[i][j], ah[i], b0h[j], b1h[j]);
                    MMA_F16(acc[i][j], al[i], b0h[j], b1h[j]);
                    MMA_F16(acc[i][j], ah[i], b0l[j], b1l[j]);
                }
        }
    }

    #pragma unroll
    for (int i = 0; i < 2; i++) {
        int row = bm + wm * 32 + i * 16 + qr;
        #pragma unroll
        for (int j = 0; j < 4; j++) {
            int col = bn + wn * 32 + j * 8 + qc * 2;
            if (col >= NN) continue;
            float b0 = bias[col], b1 = bias[col + 1];
            float v00 = acc[i][j][0] + b0, v01 = acc[i][j][1] + b1;
            float v10 = acc[i][j][2] + b0, v11 = acc[i][j][3] + b1;
            if (mode == 0) {
                *(float2*)&C[(size_t)row * ldc + col] = make_float2(v00, v01);
                *(float2*)&C[(size_t)(row + 8) * ldc + col] = make_float2(v10, v11);
            } else {
                if (mode == 1) {
                    v00 = fmaxf(v00, 0.f); v01 = fmaxf(v01, 0.f);
                    v10 = fmaxf(v10, 0.f); v11 = fmaxf(v11, 0.f);
                }
                __half h00, l00, h01, l01, h10, l10, h11, l11;
                split_h(v00, &h00, &l00); split_h(v01, &h01, &l01);
                split_h(v10, &h10, &l10); split_h(v11, &h11, &l11);
                *(__half2*)&Chi[(size_t)row * ldc + col] = __halves2half2(h00, h01);
                *(__half2*)&Clo[(size_t)row * ldc + col] = __halves2half2(l00, l01);
                *(__half2*)&Chi[(size_t)(row + 8) * ldc + col] = __halves2half2(h10, h11);
                *(__half2*)&Clo[(size_t)(row + 8) * ldc + col] = __halves2half2(l10, l11);
            }
        }
    }
}

// ---------------- init ----------------
__global__ void k_init(float* kw, float* kwh) {
    int i = blockIdx.x * blockDim.x + threadIdx.x;
    if (i < NB * HID) {
        g_h_rela[i] = 0.f; g_c_rela[i] = 0.f;
        int s = i >> 8, hh = i & 255;
        __half z = __float2half(0.f);
        g_rel_hi[(size_t)s * KREL + 462 + hh] = z;
        g_rel_lo[(size_t)s * KREL + 462 + hh] = z;
        g_tem_hi[(size_t)s * KTEM + 359 + hh] = z;
        g_tem_lo[(size_t)s * KTEM + 359 + hh] = z;
    }
    if (i < NB * WHERE) g_zw_cur[i] = 0.f;
    if (i < NB * WHAT)  g_zwt_zero[i] = 0.f;
    if (i < NB) { kw[i] = 0.f; kwh[i] = 0.f; }
}

__global__ void k_zero_pads(void) {
    int i = blockIdx.x * blockDim.x + threadIdx.x;
    if (i >= NB) return;
    __half z = __float2half(0.f);
    for (int j = 718; j < KREL; j++) { g_rel_hi[i * KREL + j] = z; g_rel_lo[i * KREL + j] = z; }
    for (int j = 615; j < KTEM; j++) { g_tem_hi[i * KTEM + j] = z; g_tem_lo[i * KTEM + j] = z; }
    for (int j = 562; j < KLW; j++)  { g_lw_hi[i * KLW + j] = z;  g_lw_lo[i * KLW + j] = z; }
    for (int j = 400; j < KGE1; j++) { g_gl_hi[i * KGE1 + j] = z; g_gl_lo[i * KGE1 + j] = z; }
    for (int j = 200; j < KGE2; j++) { g_h1_hi[i * KGE2 + j] = z; g_h1_lo[i * KGE2 + j] = z; }
}

__global__ void k_zero_pads_all(void) {
    int m = blockIdx.x * blockDim.x + threadIdx.x;
    if (m >= MALL) return;
    __half z = __float2half(0.f);
    for (int j = 400; j < KGE1; j++) { g_glA_hi[(size_t)m * KGE1 + j] = z; g_glA_lo[(size_t)m * KGE1 + j] = z; }
    for (int j = 200; j < KGE2; j++) { g_h1A_hi[(size_t)m * KGE2 + j] = z; g_h1A_lo[(size_t)m * KGE2 + j] = z; }
}

// ---------------- weight prep ----------------
__global__ void k_prep_w_hsplit(const float* __restrict__ w1, int k1,
                                const float* __restrict__ w2, int k2,
                                __half* __restrict__ whi, __half* __restrict__ wlo,
                                int kc, int nrows, int nreal) {
    int idx = blockIdx.x * blockDim.x + threadIdx.x;
    if (idx >= nrows * kc) return;
    int r = idx / kc, j = idx % kc;
    float v = 0.f;
    if (r < nreal) {
        if (j < k1) v = w1[(size_t)r * k1 + j];
        else if (j < k1 + k2 && w2) v = w2[(size_t)r * k2 + (j - k1)];
    }
    split_h(v, &whi[idx], &wlo[idx]);
}

// tem weights: columns [359,615) of Wih multiply h_rela, same as Whh -> pre-sum.
__global__ void k_prep_w_tem(const float* __restrict__ wih, const float* __restrict__ whh,
                             __half* __restrict__ whi, __half* __restrict__ wlo) {
    int idx = blockIdx.x * blockDim.x + threadIdx.x;
    if (idx >= 1024 * KTEM) return;
    int r = idx / KTEM, j = idx % KTEM;
    float v = 0.f;
    if (j < 359)      v = wih[(size_t)r * 615 + j];
    else if (j < 615) v = wih[(size_t)r * 615 + j] + whh[(size_t)r * 256 + (j - 359)];
    split_h(v, &whi[idx], &wlo[idx]);
}

__global__ void k_prep_b(const float* __restrict__ b1, const float* __restrict__ b2,
                         float* __restrict__ bc, int n) {
    int i = blockIdx.x * blockDim.x + threadIdx.x;
    if (i < n) bc[i] = b1[i] + b2[i];
}

// ---------------- glimpse helpers ----------------
__device__ __forceinline__ float samp_im(const float* __restrict__ im, int i, int y, int x) {
    if (x < 0 || x >= IMW || y < 0 || y >= IMH) return 0.f;
    return im[(size_t)i * (IMH * IMW) + y * IMW + x];
}

__device__ __forceinline__ void glimpse_body(const float* im, int i, float s, float tx, float ty,
                                             __half* dhi, __half* dlo, int tid) {
    for (int p = tid; p < 400; p += 128) {
        int a = p / GG, b = p % GG;
        float baseb = (2.f * b + 1.f) / (float)GG - 1.f;
        float basea = (2.f * a + 1.f) / (float)GG - 1.f;
        float x = s * baseb + tx;
        float y = s * basea + ty;
        float ix = ((x + 1.f) * (float)IMW - 1.f) * 0.5f;
        float iy = ((y + 1.f) * (float)IMH - 1.f) * 0.5f;
        float x0f = floorf(ix), y0f = floorf(iy);
        float wx = ix - x0f, wy = iy - y0f;
        int x0 = (int)x0f, y0 = (int)y0f;
        float v = samp_im(im, i, y0,     x0    ) * (1.f - wx) * (1.f - wy)
                + samp_im(im, i, y0,     x0 + 1) * wx         * (1.f - wy)
                + samp_im(im, i, y0 + 1, x0    ) * (1.f - wx) * wy
                + samp_im(im, i, y0 + 1, x0 + 1) * wx         * wy;
        split_h(v, &dhi[p], &dlo[p]);
    }
}

// batched glimpse-1 for all steps
__global__ void __launch_bounds__(128) k_glimpse_all(
    const float* __restrict__ im, const float* __restrict__ hid_lt,
    const float* __restrict__ w_pro, const float* __restrict__ b_pro,
    const float* __restrict__ zwhere_lt)
{
    int m = blockIdx.x;
    int t = m / NB, i = m - t * NB;
    int tid = threadIdx.x, wid = tid >> 5, lane = tid & 31;
    __shared__ float zws[3];
    if (wid < 3) {
        const float* h = hid_lt + (size_t)i * TT * HID + (size_t)t * HID;
        float s = 0.f;
        for (int k = lane; k < HID; k += 32) s += h[k] * w_pro[wid * HID + k];
        s = warp_sum(s);
        if (lane == 0)
            zws[wid] = fmaxf(s + b_pro[wid], 0.f) +
                       zwhere_lt[(size_t)i * TT * 3 + (size_t)t * 3 + wid];
    }
    __syncthreads();
    glimpse_body(im, i, zws[0], zws[1], zws[2],
                 &g_glA_hi[(size_t)m * KGE1], &g_glA_lo[(size_t)m * KGE1], tid);
}

// ---------------- FUSED: lstm_rel + lwhere + glimpse2 (block per sample, 128 thr) ----
__global__ void __launch_bounds__(128) k_fused_rel(
    const float* __restrict__ im,
    const float* __restrict__ w_lw, const float* __restrict__ b_lw,
    const float* __restrict__ zwhere_lt, const float* __restrict__ eps_w,
    int t, float* __restrict__ zw_cur, float* __restrict__ out_zwhere)
{
    int i = blockIdx.x;
    int tid = threadIdx.x, wid = tid >> 5, lane = tid & 31;
    __shared__ float hs[HID];
    __shared__ float mw6[6];
    __shared__ float zws[3];

    const float* gr = g_gates + (size_t)i * 1024;
    #pragma unroll
    for (int r = 0; r < 2; r++) {
        int hh = tid + r * 128;
        float ig = sigmoidf_(gr[hh]);
        float fg = sigmoidf_(gr[256 + hh]);
        float gg = tanhf(gr[512 + hh]);
        float og = sigmoidf_(gr[768 + hh]);
        int idx = i * HID + hh;
        float c2 = fg * g_c_rela[idx] + ig * gg;
        float h = og * tanhf(c2);
        g_c_rela[idx] = c2;
        g_h_rela[idx] = h;
        hs[hh] = h;
        __half hhi, hlo;
        split_h(h, &hhi, &hlo);
        size_t bt = (size_t)i * KTEM;
        g_tem_hi[bt + 359 + hh] = hhi; g_tem_lo[bt + 359 + hh] = hlo;
        size_t bl = (size_t)i * KLW;
        g_lw_hi[bl + 50 + hh] = hhi;   g_lw_lo[bl + 50 + hh] = hlo;
        size_t br = (size_t)i * KREL;
        g_rel_hi[br + 462 + hh] = hhi; g_rel_lo[br + 462 + hh] = hlo;
    }
    __syncthreads();

    const float* zl = zwhere_lt + (size_t)i * TT * 3 + (size_t)t * 3;
    for (int j = wid; j < 6; j += 4) {
        float s = 0.f;
        for (int k = lane; k < 259; k += 32) {
            float a = (k < 3) ? zl[k] : hs[k - 3];
            s += a * w_lw[j * 259 + k];
        }
        s = warp_sum(s);
        if (lane == 0) mw6[j] = s + b_lw[j];
    }
    __syncthreads();
    if (tid < 3) {
        float m = mw6[tid];
        float sd = softplusf_(mw6[3 + tid]) + 1e-4f;
        float e = eps_w[(size_t)i * TT * 3 + (size_t)t * 3 + tid];
        float z = m + sd * e;
        zw_cur[i * 3 + tid] = z;
        out_zwhere[(size_t)i * TT * 3 + (size_t)t * 3 + tid] = z;
        g_msw_where[i * 6 + tid] = m;
        g_msw_where[i * 6 + 3 + tid] = sd;
        zws[tid] = z;
    }
    __syncthreads();

    glimpse_body(im, i, zws[0], zws[1], zws[2],
                 &g_gl_hi[(size_t)i * KGE1], &g_gl_lo[(size_t)i * KGE1], tid);
}

// ---------------- initial concat (t=0 only) ----------------
__global__ void k_concat_both(const float* __restrict__ zwhere_lt,
                              const float* __restrict__ zw_prev,
                              const float* __restrict__ zwat_prev,
                              const float* __restrict__ zwhat_lt,
                              const float* __restrict__ hid_lt, int t) {
    int idx = blockIdx.x * blockDim.x + threadIdx.x;
    if (idx >= NB * 721) return;
    int i = idx / 721, j = idx % 721;
    if (j < 100) {
        size_t src = ((size_t)t * NB + i) * 100 + j;
        size_t dst = (size_t)i * KREL + j;
        g_rel_hi[dst] = g_enc1_hi[src];
        g_rel_lo[dst] = g_enc1_lo[src];
        return;
    }
    float v;
    __half *hi, *lo;
    if (j < 462) {
        int jj = j;
        if (jj < 103)      v = zwhere_lt[(size_t)i * TT * 3 + (size_t)t * 3 + (jj - 100)];
        else if (jj < 106) v = zw_prev[i * 3 + (jj - 103)];
        else if (jj < 156) v = zwhat_lt[(size_t)i * TT * 50 + (size_t)t * 50 + (jj - 106)];
        else if (jj < 206) v = zwat_prev[i * 50 + (jj - 156)];
        else               v = hid_lt[(size_t)i * TT * HID + (size_t)t * HID + (jj - 206)];
        hi = &g_rel_hi[(size_t)i * KREL + jj];
        lo = &g_rel_lo[(size_t)i * KREL + jj];
    } else {
        int jj = j - 462 + 100;
        if (jj < 103) v = zw_prev[i * 3 + (jj - 100)];
        else          v = hid_lt[(size_t)i * TT * HID + (size_t)t * HID + (jj - 103)];
        hi = &g_tem_hi[(size_t)i * KTEM + jj];
        lo = &g_tem_lo[(size_t)i * KTEM + jj];
    }
    split_h(v, hi, lo);
}

// ---------------- LSTM tem (h_temp split + zwhat slice) ----------------
__global__ void k_lstm_tem(float* __restrict__ htemp_out,
                           const float* __restrict__ zwhat_lt, int t) {
    int idx = blockIdx.x * blockDim.x + threadIdx.x;
    if (idx >= NB * HID) return;
    int i = idx >> 8, hh = idx & 255;
    const float* gr = g_gates + (size_t)i * 1024;
    float ig = sigmoidf_(gr[hh]);
    float fg = sigmoidf_(gr[256 + hh]);
    float gg = tanhf(gr[512 + hh]);
    float og = sigmoidf_(gr[768 + hh]);
    float c2 = fg * g_c_rela[idx] + ig * gg;
    float h = og * tanhf(c2);
    htemp_out[(size_t)i * TT * HID + (size_t)t * HID + hh] = h;
    size_t bl = (size_t)i * KLW;
    __half hhi, hlo;
    split_h(h, &hhi, &hlo);
    g_lw_hi[bl + 306 + hh] = hhi; g_lw_lo[bl + 306 + hh] = hlo;
    if (hh < 50) {
        float zv = zwhat_lt[(size_t)i * TT * 50 + (size_t)t * 50 + hh];
        split_h(zv, &g_lw_hi[bl + hh], &g_lw_lo[bl + hh]);
    }
}

// ---------------- fused what reparam + pres + KL + next-step concat ----------------
__global__ void __launch_bounds__(128) k_what_pres(
    const float* __restrict__ eps_t,
    const float* __restrict__ wp, const float* __restrict__ bp,
    const float* __restrict__ zw_cur,
    const float* __restrict__ htemp_out,
    const float* __restrict__ u_pres, const float* __restrict__ zpres_lt,
    const float* __restrict__ zwhere_lt, const float* __restrict__ zwhat_lt,
    const float* __restrict__ hid_lt,
    int t, float* __restrict__ out_zwhat, float* __restrict__ out_zpres,
    float* __restrict__ out_klwhat, float* __restrict__ out_klwhere)
{
    int gw = (blockIdx.x * blockDim.x + threadIdx.x) >> 5;
    int lane = threadIdx.x & 31;
    int wslot = threadIdx.x >> 5;
    if (gw >= NB) return;
    __shared__ float zsh[4][52];

    int j0 = lane, j1 = lane + 32;
    bool has1 = (j1 < 50);
    const float* mt = g_mt + (size_t)gw * 100;
    float m0 = mt[j0];
    float sd0 = softplusf_(mt[50 + j0]) + 1e-4f;
    float z0 = m0 + sd0 * eps_t[(size_t)gw * TT * 50 + (size_t)t * 50 + j0];
    float m1 = 0.f, sd1 = 1.f, z1 = 0.f;
    if (has1) {
        m1 = mt[j1];
        sd1 = softplusf_(mt[50 + j1]) + 1e-4f;
        z1 = m1 + sd1 * eps_t[(size_t)gw * TT * 50 + (size_t)t * 50 + j1];
    }
    out_zwhat[(size_t)gw * TT * 50 + (size_t)t * 50 + j0] = z0;
    if (has1) out_zwhat[(size_t)gw * TT * 50 + (size_t)t * 50 + j1] = z1;
    zsh[wslot][j0] = z0;
    if (has1) zsh[wslot][j1] = z1;
    __syncwarp();

    const float* ht = htemp_out + (size_t)gw * TT * HID + (size_t)t * HID;
    const float* hr = g_h_rela + (size_t)gw * HID;
    float s = 0.f;
    for (int k = lane; k < 565; k += 32) {
        float a;
        if (k < 50)       a = (k == j0) ? z0 : z1;
        else if (k < 53)  a = zw_cur[gw * 3 + (k - 50)];
        else if (k < 309) a = hr[k - 53];
        else              a = ht[k - 309];
        s += a * wp[k];
    }
    s = warp_sum(s);
    float p = sigmoidf_(s + bp[0]);
    float up = u_pres[(size_t)gw * TT + t];
    float zpl = zpres_lt[(size_t)gw * TT + t];
    float zp = (up < p * zpl) ? 1.f : 0.f;
    if (lane == 0) out_zpres[(size_t)gw * TT + t] = zp;

    float kw = -logf(sd0) + (sd0 * sd0 + m0 * m0) * 0.5f - 0.5f;
    if (has1) kw += -logf(sd1) + (sd1 * sd1 + m1 * m1) * 0.5f - 0.5f;
    kw = warp_sum(kw);

    float kh = 0.f;
    if (lane < 3) {
        float m = g_msw_where[gw * 6 + lane];
        float sd = g_msw_where[gw * 6 + 3 + lane];
        float m0p = (lane == 0) ? 0.3f : 0.f;
        float s0p = (lane == 0) ? 0.1f : 1.f;
        kh = logf(s0p / sd) + (sd * sd + (m - m0p) * (m - m0p)) / (2.f * s0p * s0p) - 0.5f;
    }
    kh = warp_sum(kh);

    if (lane == 0) {
        out_klwhat[gw]  += kw * zp;
        out_klwhere[gw] += kh * zp;
    }

    // ---- concat for step t+1 ----
    if (t + 1 < TT) {
        int tn = t + 1;
        size_t be = ((size_t)tn * NB + gw) * 100;
        size_t br = (size_t)gw * KREL;
        size_t bt2 = (size_t)gw * KTEM;
        for (int j = lane; j < 100; j += 32) {
            g_rel_hi[br + j] = g_enc1_hi[be + j];
            g_rel_lo[br + j] = g_enc1_lo[be + j];
        }
        for (int j = 100 + lane; j < 462; j += 32) {
            float v;
            if (j < 103)      v = zwhere_lt[(size_t)gw * TT * 3 + (size_t)tn * 3 + (j - 100)];
            else if (j < 106) v = zw_cur[gw * 3 + (j - 103)];
            else if (j < 156) v = zwhat_lt[(size_t)gw * TT * 50 + (size_t)tn * 50 + (j - 106)];
            else if (j < 206) v = zsh[wslot][j - 156];
            else              v = hid_lt[(size_t)gw * TT * HID + (size_t)tn * HID + (j - 206)];
            split_h(v, &g_rel_hi[br + j], &g_rel_lo[br + j]);
        }
        for (int j = 100 + lane; j < 359; j += 32) {
            float v;
            if (j < 103) v = zw_cur[gw * 3 + (j - 100)];
            else         v = hid_lt[(size_t)gw * TT * HID + (size_t)tn * HID + (j - 103)];
            split_h(v, &g_tem_hi[bt2 + j], &g_tem_lo[bt2 + j]);
        }
    }
}

// ---------------- host ----------------
static inline int cdiv(int a, int b) { return (a + b - 1) / b; }

extern "C" void kernel_launch(void* const* d_in, const int* in_sizes, int n_in,
                              void* d_out, int out_size) {
    const float* img       = (const float*)d_in[0];
    const float* zwhat_lt  = (const float*)d_in[1];
    const float* zwhere_lt = (const float*)d_in[2];
    const float* zpres_lt  = (const float*)d_in[3];
    const float* hid_lt    = (const float*)d_in[4];
    const float* eps_where = (const float*)d_in[5];
    const float* eps_what  = (const float*)d_in[6];
    const float* u_pres    = (const float*)d_in[7];
    const float* w_pro     = (const float*)d_in[8];
    const float* b_pro     = (const float*)d_in[9];
    const float* w_ge1     = (const float*)d_in[10];
    const float* b_ge1     = (const float*)d_in[11];
    const float* w_ge2     = (const float*)d_in[12];
    const float* b_ge2     = (const float*)d_in[13];
    const float* wih_rel   = (const float*)d_in[14];
    const float* whh_rel   = (const float*)d_in[15];
    const float* bih_rel   = (const float*)d_in[16];
    const float* bhh_rel   = (const float*)d_in[17];
    const float* wih_tem   = (const float*)d_in[18];
    const float* whh_tem   = (const float*)d_in[19];
    const float* bih_tem   = (const float*)d_in[20];
    const float* bhh_tem   = (const float*)d_in[21];
    const float* w_lwhere  = (const float*)d_in[22];
    const float* b_lwhere  = (const float*)d_in[23];
    const float* w_lwhat   = (const float*)d_in[24];
    const float* b_lwhat   = (const float*)d_in[25];
    const float* w_lpres   = (const float*)d_in[26];
    const float* b_lpres   = (const float*)d_in[27];

    float* out = (float*)d_out;
    float* out_zwhat   = out;
    float* out_zwhere  = out + 3276800;
    float* out_zpres   = out + 3473408;
    float* out_klwhat  = out + 3538944;
    float* out_klwhere = out + 3543040;
    float* out_htemp   = out + 3547136;

    cudaFuncSetAttribute(gemm_h3, cudaFuncAttributeMaxDynamicSharedMemorySize, H_SMEM_B);
    cudaFuncSetAttribute(gemm_h3s, cudaFuncAttributeMaxDynamicSharedMemorySize, S_SMEM_B);

    float *p_gates, *p_mt, *p_zwcur, *p_zwtzero;
    __half *p_glhi, *p_gllo, *p_h1hi, *p_h1lo, *p_lwhi, *p_lwlo;
    __half *p_glAhi, *p_glAlo, *p_h1Ahi, *p_h1Alo, *p_e1hi, *p_e1lo;
    __half *p_relhi, *p_rello, *p_temhi, *p_temlo;
    __half *p_Wrelhi, *p_Wrello, *p_Wtemhi, *p_Wtemlo;
    __half *p_Wge1hi, *p_Wge1lo, *p_Wge2hi, *p_Wge2lo, *p_Wlwhi, *p_Wlwlo;
    float *p_brel, *p_btem;
    cudaGetSymbolAddress((void**)&p_gates, g_gates);
    cudaGetSymbolAddress((void**)&p_mt, g_mt);
    cudaGetSymbolAddress((void**)&p_zwcur, g_zw_cur);
    cudaGetSymbolAddress((void**)&p_zwtzero, g_zwt_zero);
    cudaGetSymbolAddress((void**)&p_glhi, g_gl_hi);
    cudaGetSymbolAddress((void**)&p_gllo, g_gl_lo);
    cudaGetSymbolAddress((void**)&p_h1hi, g_h1_hi);
    cudaGetSymbolAddress((void**)&p_h1lo, g_h1_lo);
    cudaGetSymbolAddress((void**)&p_lwhi, g_lw_hi);
    cudaGetSymbolAddress((void**)&p_lwlo, g_lw_lo);
    cudaGetSymbolAddress((void**)&p_glAhi, g_glA_hi);
    cudaGetSymbolAddress((void**)&p_glAlo, g_glA_lo);
    cudaGetSymbolAddress((void**)&p_h1Ahi, g_h1A_hi);
    cudaGetSymbolAddress((void**)&p_h1Alo, g_h1A_lo);
    cudaGetSymbolAddress((void**)&p_e1hi, g_enc1_hi);
    cudaGetSymbolAddress((void**)&p_e1lo, g_enc1_lo);
    cudaGetSymbolAddress((void**)&p_relhi, g_rel_hi);
    cudaGetSymbolAddress((void**)&p_rello, g_rel_lo);
    cudaGetSymbolAddress((void**)&p_temhi, g_tem_hi);
    cudaGetSymbolAddress((void**)&p_temlo, g_tem_lo);
    cudaGetSymbolAddress((void**)&p_Wrelhi, g_Wrel_hi);
    cudaGetSymbolAddress((void**)&p_Wrello, g_Wrel_lo);
    cudaGetSymbolAddress((void**)&p_Wtemhi, g_Wtem_hi);
    cudaGetSymbolAddress((void**)&p_Wtemlo, g_Wtem_lo);
    cudaGetSymbolAddress((void**)&p_Wge1hi, g_Wge1_hi);
    cudaGetSymbolAddress((void**)&p_Wge1lo, g_Wge1_lo);
    cudaGetSymbolAddress((void**)&p_Wge2hi, g_Wge2_hi);
    cudaGetSymbolAddress((void**)&p_Wge2lo, g_Wge2_lo);
    cudaGetSymbolAddress((void**)&p_Wlwhi, g_Wlw_hi);
    cudaGetSymbolAddress((void**)&p_Wlwlo, g_Wlw_lo);
    cudaGetSymbolAddress((void**)&p_brel, g_brel);
    cudaGetSymbolAddress((void**)&p_btem, g_btem);

    // one-time prep
    k_init<<<cdiv(NB * HID, 256), 256>>>(out_klwhat, out_klwhere);
    k_zero_pads<<<cdiv(NB, 256), 256>>>();
    k_zero_pads_all<<<cdiv(MALL, 256), 256>>>();
    k_prep_w_hsplit<<<cdiv(1024 * KREL, 256), 256>>>(wih_rel, 462, whh_rel, 256,
                                                     p_Wrelhi, p_Wrello, KREL, 1024, 1024);
    k_prep_w_tem<<<cdiv(1024 * KTEM, 256), 256>>>(wih_tem, whh_tem, p_Wtemhi, p_Wtemlo);
    k_prep_w_hsplit<<<cdiv(256 * KGE1, 256), 256>>>(w_ge1, 400, nullptr, 0,
                                                    p_Wge1hi, p_Wge1lo, KGE1, 256, 200);
    k_prep_w_hsplit<<<cdiv(128 * KGE2, 256), 256>>>(w_ge2, 200, nullptr, 0,
                                                    p_Wge2hi, p_Wge2lo, KGE2, 128, 100);
    k_prep_w_hsplit<<<cdiv(128 * KLW, 256), 256>>>(w_lwhat, 562, nullptr, 0,
                                                   p_Wlwhi, p_Wlwlo, KLW, 128, 100);
    k_prep_b<<<cdiv(1024, 256), 256>>>(bih_rel, bhh_rel, p_brel, 1024);
    k_prep_b<<<cdiv(1024, 256), 256>>>(bih_tem, bhh_tem, p_btem, 1024);

    // batched glimpse-1 path for ALL steps (input-only dependence)
    k_glimpse_all<<<MALL, 128>>>(img, hid_lt, w_pro, b_pro, zwhere_lt);
    gemm_h3s<<<dim3(4, MALL / 64), 128, S_SMEM_B>>>(p_glAhi, p_glAlo, p_Wge1hi, p_Wge1lo,
        b_ge1, nullptr, p_h1Ahi, p_h1Alo, KGE1, NCGE1, 200, KGE2, 1);
    gemm_h3s<<<dim3(2, MALL / 64), 128, S_SMEM_B>>>(p_h1Ahi, p_h1Alo, p_Wge2hi, p_Wge2lo,
        b_ge2, nullptr, p_e1hi, p_e1lo, KGE2, NCGE2, 100, 100, 2);

    // initial concat for t=0 (zw_prev = zwt_prev = 0)
    k_concat_both<<<cdiv(NB * 721, 256), 256>>>(zwhere_lt, p_zwcur, p_zwtzero,
                                                zwhat_lt, hid_lt, 0);

    for (int t = 0; t < TT; t++) {
        gemm_h3<<<dim3(8, 32), 256, H_SMEM_B>>>(p_relhi, p_rello, p_Wrelhi, p_Wrello,
                                                p_brel, p_gates, KREL, NCREL);

        k_fused_rel<<<NB, 128>>>(img, w_lwhere, b_lwhere, zwhere_lt, eps_where, t,
                                 p_zwcur, out_zwhere);

        gemm_h3s<<<dim3(4, 64), 128, S_SMEM_B>>>(p_glhi, p_gllo, p_Wge1hi, p_Wge1lo,
            b_ge1, nullptr, p_h1hi, p_h1lo, KGE1, NCGE1, 200, KGE2, 1);
        gemm_h3s<<<dim3(2, 64), 128, S_SMEM_B>>>(p_h1hi, p_h1lo, p_Wge2hi, p_Wge2lo,
            b_ge2, nullptr, p_temhi, p_temlo, KGE2, NCGE2, 100, KTEM, 2);

        gemm_h3<<<dim3(8, 32), 256, H_SMEM_B>>>(p_temhi, p_temlo, p_Wtemhi, p_Wtemlo,
                                                p_btem, p_gates, KTEM, NCTEM);
        k_lstm_tem<<<cdiv(NB * HID, 256), 256>>>(out_htemp, zwhat_lt, t);

        gemm_h3s<<<dim3(2, 64), 128, S_SMEM_B>>>(p_lwhi, p_lwlo, p_Wlwhi, p_Wlwlo,
            b_lwhat, p_mt, nullptr, nullptr, KLW, NCLW, 100, 100, 0);

        k_what_pres<<<cdiv(NB * 32, 128), 128>>>(eps_what, w_lpres, b_lpres, p_zwcur,
                                                 out_htemp, u_pres, zpres_lt,
                                                 zwhere_lt, zwhat_lt, hid_lt,
                                                 t, out_zwhat, out_zpres,
                                                 out_klwhat, out_klwhere);
    }
    (void)in_sizes; (void)n_in; (void)out_size;
}

// round 17
// speedup vs baseline: 1.1153x; 1.1153x over previous
#include <cuda_runtime.h>
#include <cuda_fp16.h>
#include <math.h>
#include <stdint.h>

#define NB   4096
#define TT   16
#define HID  256
#define WHAT 50
#define WHERE 3
#define GG   20
#define IMH  50
#define IMW  50
#define MALL (NB * TT)   // 65536

#define KREL 736   // 718 real
#define KTEM 640   // 615 real (h_rela dedup)
#define NCREL 23
#define NCTEM 20
#define KGE1 416   // 400 real
#define KGE2 224   // 200 real
#define KLW  576   // 562 real
#define NCGE1 13
#define NCGE2 7
#define NCLW 18

// ---------------- scratch ----------------
__device__ float g_h_rela[NB * HID];
__device__ float g_c_rela[NB * HID];
__device__ float g_zw_cur[NB * WHERE];
__device__ float g_zwt_zero[NB * WHAT];
__device__ float g_gates[NB * 1024];
__device__ float g_mt[NB * 100];
__device__ float g_msw_where[NB * 6];
// fp16 split activations
__device__ __align__(16) __half g_gl_hi[NB * KGE1];
__device__ __align__(16) __half g_gl_lo[NB * KGE1];
__device__ __align__(16) __half g_h1_hi[NB * KGE2];
__device__ __align__(16) __half g_h1_lo[NB * KGE2];
__device__ __align__(16) __half g_lw_hi[NB * KLW];
__device__ __align__(16) __half g_lw_lo[NB * KLW];
__device__ __align__(16) __half g_rel_hi[NB * KREL];
__device__ __align__(16) __half g_rel_lo[NB * KREL];
__device__ __align__(16) __half g_tem_hi[NB * KTEM];
__device__ __align__(16) __half g_tem_lo[NB * KTEM];
// batched glimpse-1 path (all 16 steps)
__device__ __align__(16) __half g_glA_hi[MALL * KGE1];
__device__ __align__(16) __half g_glA_lo[MALL * KGE1];
__device__ __align__(16) __half g_h1A_hi[MALL * KGE2];
__device__ __align__(16) __half g_h1A_lo[MALL * KGE2];
__device__ __align__(16) __half g_enc1_hi[MALL * 100];
__device__ __align__(16) __half g_enc1_lo[MALL * 100];
// weights (split, padded)
__device__ __align__(16) __half g_Wrel_hi[1024 * KREL];
__device__ __align__(16) __half g_Wrel_lo[1024 * KREL];
__device__ __align__(16) __half g_Wtem_hi[1024 * KTEM];
__device__ __align__(16) __half g_Wtem_lo[1024 * KTEM];
__device__ __align__(16) __half g_Wge1_hi[256 * KGE1];
__device__ __align__(16) __half g_Wge1_lo[256 * KGE1];
__device__ __align__(16) __half g_Wge2_hi[128 * KGE2];
__device__ __align__(16) __half g_Wge2_lo[128 * KGE2];
__device__ __align__(16) __half g_Wlw_hi[128 * KLW];
__device__ __align__(16) __half g_Wlw_lo[128 * KLW];
__device__ float g_brel[1024];
__device__ float g_btem[1024];

// ---------------- helpers ----------------
__device__ __forceinline__ float sigmoidf_(float x) { return 1.f / (1.f + expf(-x)); }
__device__ __forceinline__ float softplusf_(float x) {
    return x > 0.f ? x + log1pf(expf(-x)) : log1pf(expf(x));
}
__device__ __forceinline__ float warp_sum(float v) {
    #pragma unroll
    for (int o = 16; o > 0; o >>= 1) v += __shfl_xor_sync(0xffffffffu, v, o);
    return v;
}
__device__ __forceinline__ uint32_t smem_u32(const void* p) {
    uint32_t a;
    asm("{ .reg .u64 t; cvta.to.shared.u64 t, %1; cvt.u32.u64 %0, t; }" : "=r"(a) : "l"(p));
    return a;
}
__device__ __forceinline__ void split_h(float v, __half* hi, __half* lo) {
    __half h = __float2half_rn(v);
    *hi = h;
    *lo = __float2half_rn(v - __half2float(h));
}

#define CP_ASYNC16(dst, src) \
    asm volatile("cp.async.cg.shared.global [%0], [%1], 16;" :: "r"(dst), "l"(src))
#define CP_COMMIT() asm volatile("cp.async.commit_group;")
#define CP_WAIT1()  asm volatile("cp.async.wait_group 1;")

#define MMA_F16(d, a, b) \
    asm volatile("mma.sync.aligned.m16n8k16.row.col.f32.f16.f16.f32 " \
        "{%0,%1,%2,%3}, {%4,%5,%6,%7}, {%8,%9}, {%0,%1,%2,%3};" \
        : "+f"(d[0]), "+f"(d[1]), "+f"(d[2]), "+f"(d[3]) \
        : "r"(a[0]), "r"(a[1]), "r"(a[2]), "r"(a[3]), "r"(b[0]), "r"(b[1]))

// ---------------- fp16x3 GEMM (big, 128x128): generalized epilogue ----------------
// 2-stage cp.async ring, 2 CTAs/SM. mode 0: f32 out; 1: relu+split; 2: split.
#define H_MAT_B   10240
#define H_STAGE_B (4 * H_MAT_B)
#define H_SMEM_B  (2 * H_STAGE_B)   // 81920

__global__ void __launch_bounds__(256, 2) gemm_h3(
    const __half* __restrict__ Ahi, const __half* __restrict__ Alo,
    const __half* __restrict__ Bhi, const __half* __restrict__ Blo,
    const float* __restrict__ bias, float* __restrict__ C,
    __half* __restrict__ Chi, __half* __restrict__ Clo,
    int K, int NC, int NN, int ldc, int mode)
{
    extern __shared__ char smem[];
    const uint32_t sbase = smem_u32(smem);
    const int tid = threadIdx.x;
    const int wid = tid >> 5, lane = tid & 31;
    const int wm = wid >> 2, wn = wid & 3;
    const int qr = lane >> 2, qc = lane & 3;
    const int bm = blockIdx.y * 128, bn = blockIdx.x * 128;

    auto issue = [&](int c, int s) {
        const uint32_t stb = sbase + (uint32_t)s * H_STAGE_B;
        const __half* srcs[4] = {
            Ahi + (size_t)bm * K + (size_t)c * 32,
            Alo + (size_t)bm * K + (size_t)c * 32,
            Bhi + (size_t)bn * K + (size_t)c * 32,
            Blo + (size_t)bn * K + (size_t)c * 32
        };
        #pragma unroll
        for (int mat = 0; mat < 4; mat++) {
            const __half* sp = srcs[mat];
            #pragma unroll
            for (int i = 0; i < 2; i++) {
                int g = tid + i * 256;
                int row = g >> 2, q = g & 3;
                uint32_t doff = stb + (uint32_t)mat * H_MAT_B + (uint32_t)(row * 80 + q * 16);
                CP_ASYNC16(doff, sp + (size_t)row * K + q * 8);
            }
        }
    };

    issue(0, 0); CP_COMMIT();
    issue(1, 1); CP_COMMIT();

    float acc[4][4][4] = {};

    for (int c = 0; c < NC; c++) {
        const int s = c & 1;
        CP_WAIT1();
        __syncthreads();

        const char* st = smem + (size_t)s * H_STAGE_B;
        const __half2* Ah2 = (const __half2*)st;
        const __half2* Al2 = (const __half2*)(st + H_MAT_B);
        const __half2* Bh2 = (const __half2*)(st + 2 * H_MAT_B);
        const __half2* Bl2 = (const __half2*)(st + 3 * H_MAT_B);

        #pragma unroll
        for (int ks = 0; ks < 2; ks++) {
            const int c2b = ks * 8;
            uint32_t ah[4][4], al[4][4], bh[4][2], bl[4][2];
            #pragma unroll
            for (int i = 0; i < 4; i++) {
                int m0 = wm * 64 + i * 16 + qr;
                int o0 = m0 * 20 + c2b + qc;
                int o1 = (m0 + 8) * 20 + c2b + qc;
                ah[i][0] = *(const uint32_t*)&Ah2[o0];
                ah[i][1] = *(const uint32_t*)&Ah2[o1];
                ah[i][2] = *(const uint32_t*)&Ah2[o0 + 4];
                ah[i][3] = *(const uint32_t*)&Ah2[o1 + 4];
                al[i][0] = *(const uint32_t*)&Al2[o0];
                al[i][1] = *(const uint32_t*)&Al2[o1];
                al[i][2] = *(const uint32_t*)&Al2[o0 + 4];
                al[i][3] = *(const uint32_t*)&Al2[o1 + 4];
            }
            #pragma unroll
            for (int j = 0; j < 4; j++) {
                int n0 = wn * 32 + j * 8 + qr;
                int ob = n0 * 20 + c2b + qc;
                bh[j][0] = *(const uint32_t*)&Bh2[ob];
                bh[j][1] = *(const uint32_t*)&Bh2[ob + 4];
                bl[j][0] = *(const uint32_t*)&Bl2[ob];
                bl[j][1] = *(const uint32_t*)&Bl2[ob + 4];
            }
            #pragma unroll
            for (int i = 0; i < 4; i++)
                #pragma unroll
                for (int j = 0; j < 4; j++) {
                    MMA_F16(acc[i][j], ah[i], bh[j]);
                    MMA_F16(acc[i][j], al[i], bh[j]);
                    MMA_F16(acc[i][j], ah[i], bl[j]);
                }
        }

        __syncthreads();
        if (c + 2 < NC) { issue(c + 2, s); CP_COMMIT(); }
    }

    #pragma unroll
    for (int i = 0; i < 4; i++) {
        int row = bm + wm * 64 + i * 16 + qr;
        #pragma unroll
        for (int j = 0; j < 4; j++) {
            int col = bn + wn * 32 + j * 8 + qc * 2;
            if (col >= NN) continue;
            float b0 = bias[col], b1 = bias[col + 1];
            float v00 = acc[i][j][0] + b0, v01 = acc[i][j][1] + b1;
            float v10 = acc[i][j][2] + b0, v11 = acc[i][j][3] + b1;
            if (mode == 0) {
                *(float2*)&C[(size_t)row * ldc + col] = make_float2(v00, v01);
                *(float2*)&C[(size_t)(row + 8) * ldc + col] = make_float2(v10, v11);
            } else {
                if (mode == 1) {
                    v00 = fmaxf(v00, 0.f); v01 = fmaxf(v01, 0.f);
                    v10 = fmaxf(v10, 0.f); v11 = fmaxf(v11, 0.f);
                }
                __half h00, l00, h01, l01, h10, l10, h11, l11;
                split_h(v00, &h00, &l00); split_h(v01, &h01, &l01);
                split_h(v10, &h10, &l10); split_h(v11, &h11, &l11);
                *(__half2*)&Chi[(size_t)row * ldc + col] = __halves2half2(h00, h01);
                *(__half2*)&Clo[(size_t)row * ldc + col] = __halves2half2(l00, l01);
                *(__half2*)&Chi[(size_t)(row + 8) * ldc + col] = __halves2half2(h10, h11);
                *(__half2*)&Clo[(size_t)(row + 8) * ldc + col] = __halves2half2(l10, l11);
            }
        }
    }
}

// ---------------- fp16x3 GEMM (small, 64x64): mode 0 f32; 1 relu+split; 2 split ----
#define S_MAT_B   5120
#define S_STAGE_B (4 * S_MAT_B)
#define S_SMEM_B  (3 * S_STAGE_B)

__global__ void __launch_bounds__(128) gemm_h3s(
    const __half* __restrict__ Ahi, const __half* __restrict__ Alo,
    const __half* __restrict__ Bhi, const __half* __restrict__ Blo,
    const float* __restrict__ bias, float* __restrict__ C,
    __half* __restrict__ Chi, __half* __restrict__ Clo,
    int K, int NC, int NN, int ldc, int mode)
{
    extern __shared__ char smem[];
    const uint32_t sbase = smem_u32(smem);
    const int tid = threadIdx.x;
    const int wid = tid >> 5, lane = tid & 31;
    const int wm = wid >> 1, wn = wid & 1;
    const int qr = lane >> 2, qc = lane & 3;
    const int bm = blockIdx.y * 64, bn = blockIdx.x * 64;

    auto issue = [&](int c, int s) {
        const uint32_t stb = sbase + (uint32_t)s * S_STAGE_B;
        const __half* srcs[4] = {
            Ahi + (size_t)bm * K + (size_t)c * 32,
            Alo + (size_t)bm * K + (size_t)c * 32,
            Bhi + (size_t)bn * K + (size_t)c * 32,
            Blo + (size_t)bn * K + (size_t)c * 32
        };
        #pragma unroll
        for (int mat = 0; mat < 4; mat++) {
            const __half* sp = srcs[mat];
            #pragma unroll
            for (int i = 0; i < 2; i++) {
                int g = tid + i * 128;
                int row = g >> 2, q = g & 3;
                uint32_t doff = stb + (uint32_t)mat * S_MAT_B + (uint32_t)(row * 80 + q * 16);
                CP_ASYNC16(doff, sp + (size_t)row * K + q * 8);
            }
        }
    };

    issue(0, 0); CP_COMMIT();
    if (NC > 1) issue(1, 1);
    CP_COMMIT();

    float acc[2][4][4] = {};

    for (int c = 0; c < NC; c++) {
        const int s = c - (c / 3) * 3;
        CP_WAIT1();
        __syncthreads();
        if (c + 2 < NC) issue(c + 2, (c + 2) % 3);
        CP_COMMIT();

        const char* st = smem + (size_t)s * S_STAGE_B;
        const __half2* Ah2 = (const __half2*)st;
        const __half2* Al2 = (const __half2*)(st + S_MAT_B);
        const __half2* Bh2 = (const __half2*)(st + 2 * S_MAT_B);
        const __half2* Bl2 = (const __half2*)(st + 3 * S_MAT_B);

        #pragma unroll
        for (int ks = 0; ks < 2; ks++) {
            const int c2b = ks * 8;
            uint32_t ah[2][4], al[2][4], bh[4][2], bl[4][2];
            #pragma unroll
            for (int i = 0; i < 2; i++) {
                int m0 = wm * 32 + i * 16 + qr;
                int o0 = m0 * 20 + c2b + qc;
                int o1 = (m0 + 8) * 20 + c2b + qc;
                ah[i][0] = *(const uint32_t*)&Ah2[o0];
                ah[i][1] = *(const uint32_t*)&Ah2[o1];
                ah[i][2] = *(const uint32_t*)&Ah2[o0 + 4];
                ah[i][3] = *(const uint32_t*)&Ah2[o1 + 4];
                al[i][0] = *(const uint32_t*)&Al2[o0];
                al[i][1] = *(const uint32_t*)&Al2[o1];
                al[i][2] = *(const uint32_t*)&Al2[o0 + 4];
                al[i][3] = *(const uint32_t*)&Al2[o1 + 4];
            }
            #pragma unroll
            for (int j = 0; j < 4; j++) {
                int n0 = wn * 32 + j * 8 + qr;
                int ob = n0 * 20 + c2b + qc;
                bh[j][0] = *(const uint32_t*)&Bh2[ob];
                bh[j][1] = *(const uint32_t*)&Bh2[ob + 4];
                bl[j][0] = *(const uint32_t*)&Bl2[ob];
                bl[j][1] = *(const uint32_t*)&Bl2[ob + 4];
            }
            #pragma unroll
            for (int i = 0; i < 2; i++)
                #pragma unroll
                for (int j = 0; j < 4; j++) {
                    MMA_F16(acc[i][j], ah[i], bh[j]);
                    MMA_F16(acc[i][j], al[i], bh[j]);
                    MMA_F16(acc[i][j], ah[i], bl[j]);
                }
        }
    }

    #pragma unroll
    for (int i = 0; i < 2; i++) {
        int row = bm + wm * 32 + i * 16 + qr;
        #pragma unroll
        for (int j = 0; j < 4; j++) {
            int col = bn + wn * 32 + j * 8 + qc * 2;
            if (col >= NN) continue;
            float b0 = bias[col], b1 = bias[col + 1];
            float v00 = acc[i][j][0] + b0, v01 = acc[i][j][1] + b1;
            float v10 = acc[i][j][2] + b0, v11 = acc[i][j][3] + b1;
            if (mode == 0) {
                *(float2*)&C[(size_t)row * ldc + col] = make_float2(v00, v01);
                *(float2*)&C[(size_t)(row + 8) * ldc + col] = make_float2(v10, v11);
            } else {
                if (mode == 1) {
                    v00 = fmaxf(v00, 0.f); v01 = fmaxf(v01, 0.f);
                    v10 = fmaxf(v10, 0.f); v11 = fmaxf(v11, 0.f);
                }
                __half h00, l00, h01, l01, h10, l10, h11, l11;
                split_h(v00, &h00, &l00); split_h(v01, &h01, &l01);
                split_h(v10, &h10, &l10); split_h(v11, &h11, &l11);
                *(__half2*)&Chi[(size_t)row * ldc + col] = __halves2half2(h00, h01);
                *(__half2*)&Clo[(size_t)row * ldc + col] = __halves2half2(l00, l01);
                *(__half2*)&Chi[(size_t)(row + 8) * ldc + col] = __halves2half2(h10, h11);
                *(__half2*)&Clo[(size_t)(row + 8) * ldc + col] = __halves2half2(l10, l11);
            }
        }
    }
}

// ---------------- init ----------------
__global__ void k_init(float* kw, float* kwh) {
    int i = blockIdx.x * blockDim.x + threadIdx.x;
    if (i < NB * HID) {
        g_h_rela[i] = 0.f; g_c_rela[i] = 0.f;
        int s = i >> 8, hh = i & 255;
        __half z = __float2half(0.f);
        g_rel_hi[(size_t)s * KREL + 462 + hh] = z;
        g_rel_lo[(size_t)s * KREL + 462 + hh] = z;
        g_tem_hi[(size_t)s * KTEM + 359 + hh] = z;
        g_tem_lo[(size_t)s * KTEM + 359 + hh] = z;
    }
    if (i < NB * WHERE) g_zw_cur[i] = 0.f;
    if (i < NB * WHAT)  g_zwt_zero[i] = 0.f;
    if (i < NB) { kw[i] = 0.f; kwh[i] = 0.f; }
}

__global__ void k_zero_pads(void) {
    int i = blockIdx.x * blockDim.x + threadIdx.x;
    if (i >= NB) return;
    __half z = __float2half(0.f);
    for (int j = 718; j < KREL; j++) { g_rel_hi[i * KREL + j] = z; g_rel_lo[i * KREL + j] = z; }
    for (int j = 615; j < KTEM; j++) { g_tem_hi[i * KTEM + j] = z; g_tem_lo[i * KTEM + j] = z; }
    for (int j = 562; j < KLW; j++)  { g_lw_hi[i * KLW + j] = z;  g_lw_lo[i * KLW + j] = z; }
    for (int j = 400; j < KGE1; j++) { g_gl_hi[i * KGE1 + j] = z; g_gl_lo[i * KGE1 + j] = z; }
    for (int j = 200; j < KGE2; j++) { g_h1_hi[i * KGE2 + j] = z; g_h1_lo[i * KGE2 + j] = z; }
}

__global__ void k_zero_pads_all(void) {
    int m = blockIdx.x * blockDim.x + threadIdx.x;
    if (m >= MALL) return;
    __half z = __float2half(0.f);
    for (int j = 400; j < KGE1; j++) { g_glA_hi[(size_t)m * KGE1 + j] = z; g_glA_lo[(size_t)m * KGE1 + j] = z; }
    for (int j = 200; j < KGE2; j++) { g_h1A_hi[(size_t)m * KGE2 + j] = z; g_h1A_lo[(size_t)m * KGE2 + j] = z; }
}

// ---------------- weight prep ----------------
__global__ void k_prep_w_hsplit(const float* __restrict__ w1, int k1,
                                const float* __restrict__ w2, int k2,
                                __half* __restrict__ whi, __half* __restrict__ wlo,
                                int kc, int nrows, int nreal) {
    int idx = blockIdx.x * blockDim.x + threadIdx.x;
    if (idx >= nrows * kc) return;
    int r = idx / kc, j = idx % kc;
    float v = 0.f;
    if (r < nreal) {
        if (j < k1) v = w1[(size_t)r * k1 + j];
        else if (j < k1 + k2 && w2) v = w2[(size_t)r * k2 + (j - k1)];
    }
    split_h(v, &whi[idx], &wlo[idx]);
}

// tem weights: columns [359,615) of Wih multiply h_rela, same as Whh -> pre-sum.
__global__ void k_prep_w_tem(const float* __restrict__ wih, const float* __restrict__ whh,
                             __half* __restrict__ whi, __half* __restrict__ wlo) {
    int idx = blockIdx.x * blockDim.x + threadIdx.x;
    if (idx >= 1024 * KTEM) return;
    int r = idx / KTEM, j = idx % KTEM;
    float v = 0.f;
    if (j < 359)      v = wih[(size_t)r * 615 + j];
    else if (j < 615) v = wih[(size_t)r * 615 + j] + whh[(size_t)r * 256 + (j - 359)];
    split_h(v, &whi[idx], &wlo[idx]);
}

__global__ void k_prep_b(const float* __restrict__ b1, const float* __restrict__ b2,
                         float* __restrict__ bc, int n) {
    int i = blockIdx.x * blockDim.x + threadIdx.x;
    if (i < n) bc[i] = b1[i] + b2[i];
}

// ---------------- glimpse helpers ----------------
__device__ __forceinline__ float samp_im(const float* __restrict__ im, int i, int y, int x) {
    if (x < 0 || x >= IMW || y < 0 || y >= IMH) return 0.f;
    return im[(size_t)i * (IMH * IMW) + y * IMW + x];
}

__device__ __forceinline__ void glimpse_body(const float* im, int i, float s, float tx, float ty,
                                             __half* dhi, __half* dlo, int tid) {
    for (int p = tid; p < 400; p += 128) {
        int a = p / GG, b = p % GG;
        float baseb = (2.f * b + 1.f) / (float)GG - 1.f;
        float basea = (2.f * a + 1.f) / (float)GG - 1.f;
        float x = s * baseb + tx;
        float y = s * basea + ty;
        float ix = ((x + 1.f) * (float)IMW - 1.f) * 0.5f;
        float iy = ((y + 1.f) * (float)IMH - 1.f) * 0.5f;
        float x0f = floorf(ix), y0f = floorf(iy);
        float wx = ix - x0f, wy = iy - y0f;
        int x0 = (int)x0f, y0 = (int)y0f;
        float v = samp_im(im, i, y0,     x0    ) * (1.f - wx) * (1.f - wy)
                + samp_im(im, i, y0,     x0 + 1) * wx         * (1.f - wy)
                + samp_im(im, i, y0 + 1, x0    ) * (1.f - wx) * wy
                + samp_im(im, i, y0 + 1, x0 + 1) * wx         * wy;
        split_h(v, &dhi[p], &dlo[p]);
    }
}

// batched glimpse-1 for all steps
__global__ void __launch_bounds__(128) k_glimpse_all(
    const float* __restrict__ im, const float* __restrict__ hid_lt,
    const float* __restrict__ w_pro, const float* __restrict__ b_pro,
    const float* __restrict__ zwhere_lt)
{
    int m = blockIdx.x;
    int t = m / NB, i = m - t * NB;
    int tid = threadIdx.x, wid = tid >> 5, lane = tid & 31;
    __shared__ float zws[3];
    if (wid < 3) {
        const float* h = hid_lt + (size_t)i * TT * HID + (size_t)t * HID;
        float s = 0.f;
        for (int k = lane; k < HID; k += 32) s += h[k] * w_pro[wid * HID + k];
        s = warp_sum(s);
        if (lane == 0)
            zws[wid] = fmaxf(s + b_pro[wid], 0.f) +
                       zwhere_lt[(size_t)i * TT * 3 + (size_t)t * 3 + wid];
    }
    __syncthreads();
    glimpse_body(im, i, zws[0], zws[1], zws[2],
                 &g_glA_hi[(size_t)m * KGE1], &g_glA_lo[(size_t)m * KGE1], tid);
}

// ---------------- FUSED: lstm_rel + lwhere + glimpse2 (block per sample, 128 thr) ----
__global__ void __launch_bounds__(128) k_fused_rel(
    const float* __restrict__ im,
    const float* __restrict__ w_lw, const float* __restrict__ b_lw,
    const float* __restrict__ zwhere_lt, const float* __restrict__ eps_w,
    int t, float* __restrict__ zw_cur, float* __restrict__ out_zwhere)
{
    int i = blockIdx.x;
    int tid = threadIdx.x, wid = tid >> 5, lane = tid & 31;
    __shared__ float hs[HID];
    __shared__ float mw6[6];
    __shared__ float zws[3];

    const float* gr = g_gates + (size_t)i * 1024;
    #pragma unroll
    for (int r = 0; r < 2; r++) {
        int hh = tid + r * 128;
        float ig = sigmoidf_(gr[hh]);
        float fg = sigmoidf_(gr[256 + hh]);
        float gg = tanhf(gr[512 + hh]);
        float og = sigmoidf_(gr[768 + hh]);
        int idx = i * HID + hh;
        float c2 = fg * g_c_rela[idx] + ig * gg;
        float h = og * tanhf(c2);
        g_c_rela[idx] = c2;
        g_h_rela[idx] = h;
        hs[hh] = h;
        __half hhi, hlo;
        split_h(h, &hhi, &hlo);
        size_t bt = (size_t)i * KTEM;
        g_tem_hi[bt + 359 + hh] = hhi; g_tem_lo[bt + 359 + hh] = hlo;
        size_t bl = (size_t)i * KLW;
        g_lw_hi[bl + 50 + hh] = hhi;   g_lw_lo[bl + 50 + hh] = hlo;
        size_t br = (size_t)i * KREL;
        g_rel_hi[br + 462 + hh] = hhi; g_rel_lo[br + 462 + hh] = hlo;
    }
    __syncthreads();

    const float* zl = zwhere_lt + (size_t)i * TT * 3 + (size_t)t * 3;
    for (int j = wid; j < 6; j += 4) {
        float s = 0.f;
        for (int k = lane; k < 259; k += 32) {
            float a = (k < 3) ? zl[k] : hs[k - 3];
            s += a * w_lw[j * 259 + k];
        }
        s = warp_sum(s);
        if (lane == 0) mw6[j] = s + b_lw[j];
    }
    __syncthreads();
    if (tid < 3) {
        float m = mw6[tid];
        float sd = softplusf_(mw6[3 + tid]) + 1e-4f;
        float e = eps_w[(size_t)i * TT * 3 + (size_t)t * 3 + tid];
        float z = m + sd * e;
        zw_cur[i * 3 + tid] = z;
        out_zwhere[(size_t)i * TT * 3 + (size_t)t * 3 + tid] = z;
        g_msw_where[i * 6 + tid] = m;
        g_msw_where[i * 6 + 3 + tid] = sd;
        zws[tid] = z;
    }
    __syncthreads();

    glimpse_body(im, i, zws[0], zws[1], zws[2],
                 &g_gl_hi[(size_t)i * KGE1], &g_gl_lo[(size_t)i * KGE1], tid);
}

// ---------------- initial concat (t=0 only) ----------------
__global__ void k_concat_both(const float* __restrict__ zwhere_lt,
                              const float* __restrict__ zw_prev,
                              const float* __restrict__ zwat_prev,
                              const float* __restrict__ zwhat_lt,
                              const float* __restrict__ hid_lt, int t) {
    int idx = blockIdx.x * blockDim.x + threadIdx.x;
    if (idx >= NB * 721) return;
    int i = idx / 721, j = idx % 721;
    if (j < 100) {
        size_t src = ((size_t)t * NB + i) * 100 + j;
        size_t dst = (size_t)i * KREL + j;
        g_rel_hi[dst] = g_enc1_hi[src];
        g_rel_lo[dst] = g_enc1_lo[src];
        return;
    }
    float v;
    __half *hi, *lo;
    if (j < 462) {
        int jj = j;
        if (jj < 103)      v = zwhere_lt[(size_t)i * TT * 3 + (size_t)t * 3 + (jj - 100)];
        else if (jj < 106) v = zw_prev[i * 3 + (jj - 103)];
        else if (jj < 156) v = zwhat_lt[(size_t)i * TT * 50 + (size_t)t * 50 + (jj - 106)];
        else if (jj < 206) v = zwat_prev[i * 50 + (jj - 156)];
        else               v = hid_lt[(size_t)i * TT * HID + (size_t)t * HID + (jj - 206)];
        hi = &g_rel_hi[(size_t)i * KREL + jj];
        lo = &g_rel_lo[(size_t)i * KREL + jj];
    } else {
        int jj = j - 462 + 100;
        if (jj < 103) v = zw_prev[i * 3 + (jj - 100)];
        else          v = hid_lt[(size_t)i * TT * HID + (size_t)t * HID + (jj - 103)];
        hi = &g_tem_hi[(size_t)i * KTEM + jj];
        lo = &g_tem_lo[(size_t)i * KTEM + jj];
    }
    split_h(v, hi, lo);
}

// ---------------- LSTM tem (h_temp split + zwhat slice) ----------------
__global__ void k_lstm_tem(float* __restrict__ htemp_out,
                           const float* __restrict__ zwhat_lt, int t) {
    int idx = blockIdx.x * blockDim.x + threadIdx.x;
    if (idx >= NB * HID) return;
    int i = idx >> 8, hh = idx & 255;
    const float* gr = g_gates + (size_t)i * 1024;
    float ig = sigmoidf_(gr[hh]);
    float fg = sigmoidf_(gr[256 + hh]);
    float gg = tanhf(gr[512 + hh]);
    float og = sigmoidf_(gr[768 + hh]);
    float c2 = fg * g_c_rela[idx] + ig * gg;
    float h = og * tanhf(c2);
    htemp_out[(size_t)i * TT * HID + (size_t)t * HID + hh] = h;
    size_t bl = (size_t)i * KLW;
    __half hhi, hlo;
    split_h(h, &hhi, &hlo);
    g_lw_hi[bl + 306 + hh] = hhi; g_lw_lo[bl + 306 + hh] = hlo;
    if (hh < 50) {
        float zv = zwhat_lt[(size_t)i * TT * 50 + (size_t)t * 50 + hh];
        split_h(zv, &g_lw_hi[bl + hh], &g_lw_lo[bl + hh]);
    }
}

// ---------------- fused what reparam + pres + KL + next-step concat ----------------
__global__ void __launch_bounds__(128) k_what_pres(
    const float* __restrict__ eps_t,
    const float* __restrict__ wp, const float* __restrict__ bp,
    const float* __restrict__ zw_cur,
    const float* __restrict__ htemp_out,
    const float* __restrict__ u_pres, const float* __restrict__ zpres_lt,
    const float* __restrict__ zwhere_lt, const float* __restrict__ zwhat_lt,
    const float* __restrict__ hid_lt,
    int t, float* __restrict__ out_zwhat, float* __restrict__ out_zpres,
    float* __restrict__ out_klwhat, float* __restrict__ out_klwhere)
{
    int gw = (blockIdx.x * blockDim.x + threadIdx.x) >> 5;
    int lane = threadIdx.x & 31;
    int wslot = threadIdx.x >> 5;
    if (gw >= NB) return;
    __shared__ float zsh[4][52];

    int j0 = lane, j1 = lane + 32;
    bool has1 = (j1 < 50);
    const float* mt = g_mt + (size_t)gw * 100;
    float m0 = mt[j0];
    float sd0 = softplusf_(mt[50 + j0]) + 1e-4f;
    float z0 = m0 + sd0 * eps_t[(size_t)gw * TT * 50 + (size_t)t * 50 + j0];
    float m1 = 0.f, sd1 = 1.f, z1 = 0.f;
    if (has1) {
        m1 = mt[j1];
        sd1 = softplusf_(mt[50 + j1]) + 1e-4f;
        z1 = m1 + sd1 * eps_t[(size_t)gw * TT * 50 + (size_t)t * 50 + j1];
    }
    out_zwhat[(size_t)gw * TT * 50 + (size_t)t * 50 + j0] = z0;
    if (has1) out_zwhat[(size_t)gw * TT * 50 + (size_t)t * 50 + j1] = z1;
    zsh[wslot][j0] = z0;
    if (has1) zsh[wslot][j1] = z1;
    __syncwarp();

    const float* ht = htemp_out + (size_t)gw * TT * HID + (size_t)t * HID;
    const float* hr = g_h_rela + (size_t)gw * HID;
    float s = 0.f;
    for (int k = lane; k < 565; k += 32) {
        float a;
        if (k < 50)       a = (k == j0) ? z0 : z1;
        else if (k < 53)  a = zw_cur[gw * 3 + (k - 50)];
        else if (k < 309) a = hr[k - 53];
        else              a = ht[k - 309];
        s += a * wp[k];
    }
    s = warp_sum(s);
    float p = sigmoidf_(s + bp[0]);
    float up = u_pres[(size_t)gw * TT + t];
    float zpl = zpres_lt[(size_t)gw * TT + t];
    float zp = (up < p * zpl) ? 1.f : 0.f;
    if (lane == 0) out_zpres[(size_t)gw * TT + t] = zp;

    float kw = -logf(sd0) + (sd0 * sd0 + m0 * m0) * 0.5f - 0.5f;
    if (has1) kw += -logf(sd1) + (sd1 * sd1 + m1 * m1) * 0.5f - 0.5f;
    kw = warp_sum(kw);

    float kh = 0.f;
    if (lane < 3) {
        float m = g_msw_where[gw * 6 + lane];
        float sd = g_msw_where[gw * 6 + 3 + lane];
        float m0p = (lane == 0) ? 0.3f : 0.f;
        float s0p = (lane == 0) ? 0.1f : 1.f;
        kh = logf(s0p / sd) + (sd * sd + (m - m0p) * (m - m0p)) / (2.f * s0p * s0p) - 0.5f;
    }
    kh = warp_sum(kh);

    if (lane == 0) {
        out_klwhat[gw]  += kw * zp;
        out_klwhere[gw] += kh * zp;
    }

    // ---- concat for step t+1 ----
    if (t + 1 < TT) {
        int tn = t + 1;
        size_t be = ((size_t)tn * NB + gw) * 100;
        size_t br = (size_t)gw * KREL;
        size_t bt2 = (size_t)gw * KTEM;
        for (int j = lane; j < 100; j += 32) {
            g_rel_hi[br + j] = g_enc1_hi[be + j];
            g_rel_lo[br + j] = g_enc1_lo[be + j];
        }
        for (int j = 100 + lane; j < 462; j += 32) {
            float v;
            if (j < 103)      v = zwhere_lt[(size_t)gw * TT * 3 + (size_t)tn * 3 + (j - 100)];
            else if (j < 106) v = zw_cur[gw * 3 + (j - 103)];
            else if (j < 156) v = zwhat_lt[(size_t)gw * TT * 50 + (size_t)tn * 50 + (j - 106)];
            else if (j < 206) v = zsh[wslot][j - 156];
            else              v = hid_lt[(size_t)gw * TT * HID + (size_t)tn * HID + (j - 206)];
            split_h(v, &g_rel_hi[br + j], &g_rel_lo[br + j]);
        }
        for (int j = 100 + lane; j < 359; j += 32) {
            float v;
            if (j < 103) v = zw_cur[gw * 3 + (j - 100)];
            else         v = hid_lt[(size_t)gw * TT * HID + (size_t)tn * HID + (j - 103)];
            split_h(v, &g_tem_hi[bt2 + j], &g_tem_lo[bt2 + j]);
        }
    }
}

// ---------------- host ----------------
static inline int cdiv(int a, int b) { return (a + b - 1) / b; }

extern "C" void kernel_launch(void* const* d_in, const int* in_sizes, int n_in,
                              void* d_out, int out_size) {
    const float* img       = (const float*)d_in[0];
    const float* zwhat_lt  = (const float*)d_in[1];
    const float* zwhere_lt = (const float*)d_in[2];
    const float* zpres_lt  = (const float*)d_in[3];
    const float* hid_lt    = (const float*)d_in[4];
    const float* eps_where = (const float*)d_in[5];
    const float* eps_what  = (const float*)d_in[6];
    const float* u_pres    = (const float*)d_in[7];
    const float* w_pro     = (const float*)d_in[8];
    const float* b_pro     = (const float*)d_in[9];
    const float* w_ge1     = (const float*)d_in[10];
    const float* b_ge1     = (const float*)d_in[11];
    const float* w_ge2     = (const float*)d_in[12];
    const float* b_ge2     = (const float*)d_in[13];
    const float* wih_rel   = (const float*)d_in[14];
    const float* whh_rel   = (const float*)d_in[15];
    const float* bih_rel   = (const float*)d_in[16];
    const float* bhh_rel   = (const float*)d_in[17];
    const float* wih_tem   = (const float*)d_in[18];
    const float* whh_tem   = (const float*)d_in[19];
    const float* bih_tem   = (const float*)d_in[20];
    const float* bhh_tem   = (const float*)d_in[21];
    const float* w_lwhere  = (const float*)d_in[22];
    const float* b_lwhere  = (const float*)d_in[23];
    const float* w_lwhat   = (const float*)d_in[24];
    const float* b_lwhat   = (const float*)d_in[25];
    const float* w_lpres   = (const float*)d_in[26];
    const float* b_lpres   = (const float*)d_in[27];

    float* out = (float*)d_out;
    float* out_zwhat   = out;
    float* out_zwhere  = out + 3276800;
    float* out_zpres   = out + 3473408;
    float* out_klwhat  = out + 3538944;
    float* out_klwhere = out + 3543040;
    float* out_htemp   = out + 3547136;

    cudaFuncSetAttribute(gemm_h3, cudaFuncAttributeMaxDynamicSharedMemorySize, H_SMEM_B);
    cudaFuncSetAttribute(gemm_h3s, cudaFuncAttributeMaxDynamicSharedMemorySize, S_SMEM_B);

    float *p_gates, *p_mt, *p_zwcur, *p_zwtzero;
    __half *p_glhi, *p_gllo, *p_h1hi, *p_h1lo, *p_lwhi, *p_lwlo;
    __half *p_glAhi, *p_glAlo, *p_h1Ahi, *p_h1Alo, *p_e1hi, *p_e1lo;
    __half *p_relhi, *p_rello, *p_temhi, *p_temlo;
    __half *p_Wrelhi, *p_Wrello, *p_Wtemhi, *p_Wtemlo;
    __half *p_Wge1hi, *p_Wge1lo, *p_Wge2hi, *p_Wge2lo, *p_Wlwhi, *p_Wlwlo;
    float *p_brel, *p_btem;
    cudaGetSymbolAddress((void**)&p_gates, g_gates);
    cudaGetSymbolAddress((void**)&p_mt, g_mt);
    cudaGetSymbolAddress((void**)&p_zwcur, g_zw_cur);
    cudaGetSymbolAddress((void**)&p_zwtzero, g_zwt_zero);
    cudaGetSymbolAddress((void**)&p_glhi, g_gl_hi);
    cudaGetSymbolAddress((void**)&p_gllo, g_gl_lo);
    cudaGetSymbolAddress((void**)&p_h1hi, g_h1_hi);
    cudaGetSymbolAddress((void**)&p_h1lo, g_h1_lo);
    cudaGetSymbolAddress((void**)&p_lwhi, g_lw_hi);
    cudaGetSymbolAddress((void**)&p_lwlo, g_lw_lo);
    cudaGetSymbolAddress((void**)&p_glAhi, g_glA_hi);
    cudaGetSymbolAddress((void**)&p_glAlo, g_glA_lo);
    cudaGetSymbolAddress((void**)&p_h1Ahi, g_h1A_hi);
    cudaGetSymbolAddress((void**)&p_h1Alo, g_h1A_lo);
    cudaGetSymbolAddress((void**)&p_e1hi, g_enc1_hi);
    cudaGetSymbolAddress((void**)&p_e1lo, g_enc1_lo);
    cudaGetSymbolAddress((void**)&p_relhi, g_rel_hi);
    cudaGetSymbolAddress((void**)&p_rello, g_rel_lo);
    cudaGetSymbolAddress((void**)&p_temhi, g_tem_hi);
    cudaGetSymbolAddress((void**)&p_temlo, g_tem_lo);
    cudaGetSymbolAddress((void**)&p_Wrelhi, g_Wrel_hi);
    cudaGetSymbolAddress((void**)&p_Wrello, g_Wrel_lo);
    cudaGetSymbolAddress((void**)&p_Wtemhi, g_Wtem_hi);
    cudaGetSymbolAddress((void**)&p_Wtemlo, g_Wtem_lo);
    cudaGetSymbolAddress((void**)&p_Wge1hi, g_Wge1_hi);
    cudaGetSymbolAddress((void**)&p_Wge1lo, g_Wge1_lo);
    cudaGetSymbolAddress((void**)&p_Wge2hi, g_Wge2_hi);
    cudaGetSymbolAddress((void**)&p_Wge2lo, g_Wge2_lo);
    cudaGetSymbolAddress((void**)&p_Wlwhi, g_Wlw_hi);
    cudaGetSymbolAddress((void**)&p_Wlwlo, g_Wlw_lo);
    cudaGetSymbolAddress((void**)&p_brel, g_brel);
    cudaGetSymbolAddress((void**)&p_btem, g_btem);

    // one-time prep
    k_init<<<cdiv(NB * HID, 256), 256>>>(out_klwhat, out_klwhere);
    k_zero_pads<<<cdiv(NB, 256), 256>>>();
    k_zero_pads_all<<<cdiv(MALL, 256), 256>>>();
    k_prep_w_hsplit<<<cdiv(1024 * KREL, 256), 256>>>(wih_rel, 462, whh_rel, 256,
                                                     p_Wrelhi, p_Wrello, KREL, 1024, 1024);
    k_prep_w_tem<<<cdiv(1024 * KTEM, 256), 256>>>(wih_tem, whh_tem, p_Wtemhi, p_Wtemlo);
    k_prep_w_hsplit<<<cdiv(256 * KGE1, 256), 256>>>(w_ge1, 400, nullptr, 0,
                                                    p_Wge1hi, p_Wge1lo, KGE1, 256, 200);
    k_prep_w_hsplit<<<cdiv(128 * KGE2, 256), 256>>>(w_ge2, 200, nullptr, 0,
                                                    p_Wge2hi, p_Wge2lo, KGE2, 128, 100);
    k_prep_w_hsplit<<<cdiv(128 * KLW, 256), 256>>>(w_lwhat, 562, nullptr, 0,
                                                   p_Wlwhi, p_Wlwlo, KLW, 128, 100);
    k_prep_b<<<cdiv(1024, 256), 256>>>(bih_rel, bhh_rel, p_brel, 1024);
    k_prep_b<<<cdiv(1024, 256), 256>>>(bih_tem, bhh_tem, p_btem, 1024);

    // batched glimpse-1 path for ALL steps (big-tile GEMMs, M = 65536)
    k_glimpse_all<<<MALL, 128>>>(img, hid_lt, w_pro, b_pro, zwhere_lt);
    gemm_h3<<<dim3(2, MALL / 128), 256, H_SMEM_B>>>(p_glAhi, p_glAlo, p_Wge1hi, p_Wge1lo,
        b_ge1, nullptr, p_h1Ahi, p_h1Alo, KGE1, NCGE1, 200, KGE2, 1);
    gemm_h3<<<dim3(1, MALL / 128), 256, H_SMEM_B>>>(p_h1Ahi, p_h1Alo, p_Wge2hi, p_Wge2lo,
        b_ge2, nullptr, p_e1hi, p_e1lo, KGE2, NCGE2, 100, 100, 2);

    // initial concat for t=0 (zw_prev = zwt_prev = 0)
    k_concat_both<<<cdiv(NB * 721, 256), 256>>>(zwhere_lt, p_zwcur, p_zwtzero,
                                                zwhat_lt, hid_lt, 0);

    for (int t = 0; t < TT; t++) {
        gemm_h3<<<dim3(8, 32), 256, H_SMEM_B>>>(p_relhi, p_rello, p_Wrelhi, p_Wrello,
            p_brel, p_gates, nullptr, nullptr, KREL, NCREL, 1024, 1024, 0);

        k_fused_rel<<<NB, 128>>>(img, w_lwhere, b_lwhere, zwhere_lt, eps_where, t,
                                 p_zwcur, out_zwhere);

        gemm_h3s<<<dim3(4, 64), 128, S_SMEM_B>>>(p_glhi, p_gllo, p_Wge1hi, p_Wge1lo,
            b_ge1, nullptr, p_h1hi, p_h1lo, KGE1, NCGE1, 200, KGE2, 1);
        gemm_h3s<<<dim3(2, 64), 128, S_SMEM_B>>>(p_h1hi, p_h1lo, p_Wge2hi, p_Wge2lo,
            b_ge2, nullptr, p_temhi, p_temlo, KGE2, NCGE2, 100, KTEM, 2);

        gemm_h3<<<dim3(8, 32), 256, H_SMEM_B>>>(p_temhi, p_temlo, p_Wtemhi, p_Wtemlo,
            p_btem, p_gates, nullptr, nullptr, KTEM, NCTEM, 1024, 1024, 0);
        k_lstm_tem<<<cdiv(NB * HID, 256), 256>>>(out_htemp, zwhat_lt, t);

        gemm_h3s<<<dim3(2, 64), 128, S_SMEM_B>>>(p_lwhi, p_lwlo, p_Wlwhi, p_Wlwlo,
            b_lwhat, p_mt, nullptr, nullptr, KLW, NCLW, 100, 100, 0);

        k_what_pres<<<cdiv(NB * 32, 128), 128>>>(eps_what, w_lpres, b_lpres, p_zwcur,
                                                 out_htemp, u_pres, zpres_lt,
                                                 zwhere_lt, zwhat_lt, hid_lt,
                                                 t, out_zwhat, out_zpres,
                                                 out_klwhat, out_klwhere);
    }
    (void)in_sizes; (void)n_in; (void)out_size;
}